// round 16
// baseline (speedup 1.0000x reference)
#include <cuda_runtime.h>
#include <cuda_fp16.h>
#include <math.h>
#include <stdint.h>

#define Tc 4096
#define Dc 512
#define Sc 1024
#define Bc 4
#define Hc 8
#define HEADc 64
#define Ec 8
#define DHc 2048
#define Lc 2
#define QKVN 1536
#define MAXBLK 72

typedef __half half_t;

// ---------------- scratch (device globals) ---------------------------------
__device__ float  g_h[Tc * Dc];
__device__ half_t g_h16[Tc * Dc];
__device__ half_t g_qkv16[(size_t)Tc * QKVN];
__device__ half_t g_ao16[Tc * Dc];
__device__ half_t g_hm16[(size_t)2 * Tc * DHc];
__device__ half_t g_wqkvt16[(size_t)Lc * QKVN * Dc];
__device__ half_t g_wot16[Lc * Dc * Dc];
__device__ half_t g_w1t16[(size_t)Lc * Ec * Dc * DHc];
__device__ half_t g_w2t16[(size_t)Lc * Ec * Dc * DHc];
__device__ float  g_gate[Tc * 2];
__device__ int    g_topi[Tc * 2];
__device__ int    g_cnt[Ec], g_cur[Ec], g_off[Ec];
__device__ int    g_tok[2 * Tc];
__device__ int    g_blk_e[MAXBLK], g_blk_m[MAXBLK], g_nblk;

// ================= low-level helpers ========================================
__device__ __forceinline__ void gdc_wait() {
    asm volatile("griddepcontrol.wait;" ::: "memory");
}
__device__ __forceinline__ uint32_t smem_u32(const void* p) {
    uint32_t a;
    asm("{ .reg .u64 t; cvta.to.shared.u64 t, %1; cvt.u32.u64 %0, t; }"
        : "=r"(a) : "l"(p));
    return a;
}
#define SWZ(o) ((o) ^ (((o) >> 3) & 0x70))
#define CP16(dst, src, sz) \
    asm volatile("cp.async.cg.shared.global [%0], [%1], 16, %2;" \
                 :: "r"(dst), "l"(src), "r"(sz) : "memory")
#define CP_COMMIT() asm volatile("cp.async.commit_group;" ::: "memory")

__device__ __forceinline__ void ldsm4(uint32_t* r, uint32_t addr) {
    asm volatile("ldmatrix.sync.aligned.m8n8.x4.shared.b16 {%0,%1,%2,%3}, [%4];"
                 : "=r"(r[0]), "=r"(r[1]), "=r"(r[2]), "=r"(r[3]) : "r"(addr));
}
__device__ __forceinline__ void ldsm4t(uint32_t* r, uint32_t addr) {
    asm volatile("ldmatrix.sync.aligned.m8n8.x4.trans.shared.b16 {%0,%1,%2,%3}, [%4];"
                 : "=r"(r[0]), "=r"(r[1]), "=r"(r[2]), "=r"(r[3]) : "r"(addr));
}
__device__ __forceinline__ void mma_f16(float* d, const uint32_t* a,
                                        uint32_t b0, uint32_t b1) {
    asm volatile(
        "mma.sync.aligned.m16n8k16.row.col.f32.f16.f16.f32 "
        "{%0,%1,%2,%3}, {%4,%5,%6,%7}, {%8,%9}, {%0,%1,%2,%3};"
        : "+f"(d[0]), "+f"(d[1]), "+f"(d[2]), "+f"(d[3])
        : "r"(a[0]), "r"(a[1]), "r"(a[2]), "r"(a[3]), "r"(b0), "r"(b1));
}
__device__ __forceinline__ uint32_t pack2h(float x0, float x1) {
    __half2 h = __floats2half2_rn(x0, x1);
    return *(uint32_t*)&h;
}

// ================= pipelined fp16 tensor GEMM (3-stage, 2 CTAs/SM) ==========
// BN: 128 or 64 n-tile. PDL=1 (AMODE==0 only): preload B of stages 0/1
// before griddepcontrol.wait — overlaps weight fetch with predecessor tail.
// EPI: 1 fp32+bias+Resid->C; 2 gelu(+bias)->fp16 grouped;
//      3 gate-weighted atomicAdd into fp32 out; 4 fp16 plain
// AMODE: 0 direct; 1 grouped + gather rows via g_tok>>1; 2 grouped rows off+m
#define TG_SMEM_BN(BN) (3 * (16384 + (BN) * 128) + 1024)
template <int BN, int EPI, int AMODE, int PDL>
__global__ void __launch_bounds__(256, 2) tgemm(
    int K,
    const half_t* __restrict__ A, int lda,
    const half_t* __restrict__ B, int ldb,
    float* __restrict__ C, half_t* __restrict__ C16, int ldc,
    const float* __restrict__ bias, const float* __restrict__ Resid,
    long wstride, long bstride)
{
    constexpr int NWN = BN / 32, NWM = 8 / NWN, MT = 128 / (16 * NWM);
    constexpr uint32_t ASZ = 16384u;
    constexpr uint32_t STG = ASZ + (uint32_t)BN * 128u;
    extern __shared__ char dsm[];
    __shared__ int stok_s[128];
    uint32_t sbb = smem_u32(dsm);
    uint32_t tb = (sbb + 1023) & ~1023u;
    int tid = threadIdx.x, wid = tid >> 5, lid = tid & 31;

    int cnt = 0, off = 0, m0, n0;
    n0 = blockIdx.x * BN;

    // B loader (weights / independent operand)
    auto load_B = [&](int c, int st) {
        uint32_t base = tb + (uint32_t)st * STG;
        int k0 = c << 6;
#pragma unroll
        for (int i = 0; i < BN / 32; i++) {
            int idx = tid + (i << 8);
            int row = idx >> 3, c16 = idx & 7;
            uint32_t d = SWZ((uint32_t)(row * 128 + c16 * 16));
            long so = (long)(n0 + row) * ldb + k0 + c16 * 8;
            CP16(base + ASZ + d, B + so, 16);
        }
    };

    if (PDL) {          // AMODE == 0 guaranteed: B/n0 independent of predecessor
        m0 = blockIdx.y * 128;
        load_B(0, 0);
        load_B(1, 1);
        gdc_wait();
    } else {
        if (AMODE != 0) {
            int by = blockIdx.y;
            if (by >= g_nblk) return;
            int e = g_blk_e[by];
            cnt = g_cnt[e]; off = g_off[e];
            m0 = g_blk_m[by] * 128;
            B += (long)e * wstride;
            bias += (long)e * bstride;
        } else {
            m0 = blockIdx.y * 128;
        }
        if (AMODE == 1 && tid < 128) {
            int i = m0 + tid;
            stok_s[tid] = (i < cnt) ? (g_tok[off + i] >> 1) : -1;
        }
        if (AMODE == 2 && tid < 128) {
            int i = m0 + tid;
            stok_s[tid] = (i < cnt) ? g_tok[off + i] : -1;
        }
        if (AMODE != 0) __syncthreads();
    }

    auto load_A = [&](int c, int st) {
        uint32_t base = tb + (uint32_t)st * STG;
        int k0 = c << 6;
#pragma unroll
        for (int i = 0; i < 4; i++) {
            int idx = tid + (i << 8);
            int row = idx >> 3, c16 = idx & 7;
            uint32_t d = SWZ((uint32_t)(row * 128 + c16 * 16));
            long so; uint32_t sz = 16;
            if (AMODE == 0) so = (long)(m0 + row) * lda + k0 + c16 * 8;
            else if (AMODE == 1) {
                int tk = stok_s[row];
                if (tk < 0) { sz = 0; tk = 0; }
                so = (long)tk * lda + k0 + c16 * 8;
            } else {
                if (stok_s[row] < 0) { sz = 0; so = 0; }
                else so = (long)(off + m0 + row) * lda + k0 + c16 * 8;
            }
            CP16(base + d, A + so, sz);
        }
    };
    auto load_stage = [&](int c, int st) {
        load_A(c, st); load_B(c, st); CP_COMMIT();
    };

    int wm = (wid / NWN) * (MT * 16), wn = (wid % NWN) * 32;
    int a_row = wm + (lid & 15), a_cb = (lid >> 4) << 4;
    int b_row = wn + ((lid >> 4) << 3) + (lid & 7), b_cb = ((lid >> 3) & 1) << 4;
    float acc[MT][4][4] = {};

    int nch = K >> 6;
    if (PDL) {
        load_A(0, 0); CP_COMMIT();   // group0 = {B0, B1, A0}
        load_A(1, 1); CP_COMMIT();   // group1 = {A1}
    } else {
        load_stage(0, 0);
        if (nch > 1) load_stage(1, 1);
    }
    int st = 0;
    for (int c = 0; c < nch; c++) {
        if (c + 2 < nch) {
            load_stage(c + 2, (st + 2) % 3);
            asm volatile("cp.async.wait_group 2;" ::: "memory");
        } else if (c + 1 < nch) {
            asm volatile("cp.async.wait_group 1;" ::: "memory");
        } else {
            asm volatile("cp.async.wait_group 0;" ::: "memory");
        }
        __syncthreads();
        uint32_t base = tb + (uint32_t)st * STG;

        uint32_t bF[2][2][4];
#pragma unroll
        for (int g = 0; g < 2; g++) {
            uint32_t o = SWZ((uint32_t)((b_row + g * 16) * 128 + 0 + b_cb));
            ldsm4(bF[0][g], base + ASZ + o);
        }
#pragma unroll
        for (int ks = 0; ks < 4; ks++) {
            int cur = ks & 1, nxt = cur ^ 1;
            if (ks < 3) {
                int kb = (ks + 1) * 32;
#pragma unroll
                for (int g = 0; g < 2; g++) {
                    uint32_t o = SWZ((uint32_t)((b_row + g * 16) * 128 + kb + b_cb));
                    ldsm4(bF[nxt][g], base + ASZ + o);
                }
            }
            int kb = ks * 32;
#pragma unroll
            for (int mt = 0; mt < MT; mt++) {
                uint32_t aF[4];
                uint32_t o = SWZ((uint32_t)((a_row + mt * 16) * 128 + kb + a_cb));
                ldsm4(aF, base + o);
#pragma unroll
                for (int nt = 0; nt < 4; nt++) {
                    int g = nt >> 1, pr = (nt & 1) * 2;
                    mma_f16(acc[mt][nt], aF, bF[cur][g][pr], bF[cur][g][pr + 1]);
                }
            }
        }
        __syncthreads();
        st = (st + 1) % 3;
    }

    // ---- register epilogue ----
    int lr = lid >> 2, lc = (lid & 3) * 2;
#pragma unroll
    for (int mt = 0; mt < MT; mt++) {
#pragma unroll
        for (int half = 0; half < 2; half++) {
            int lrow = wm + mt * 16 + lr + half * 8;
            int grow = m0 + lrow;
#pragma unroll
            for (int nt = 0; nt < 4; nt++) {
                float v0 = acc[mt][nt][half * 2 + 0];
                float v1 = acc[mt][nt][half * 2 + 1];
                int gc = n0 + wn + nt * 8 + lc;
                if (EPI == 1) {
                    long idx = (long)grow * ldc + gc;
                    float2 old = *(const float2*)&Resid[idx];
                    *(float2*)&C[idx] = make_float2(v0 + bias[gc] + old.x,
                                                    v1 + bias[gc + 1] + old.y);
                } else if (EPI == 2) {
                    if (stok_s[lrow] >= 0) {
                        float t0 = v0 + bias[gc], t1 = v1 + bias[gc + 1];
                        float o0 = 0.5f * t0 * (1.f + erff(t0 * 0.70710678118654752f));
                        float o1 = 0.5f * t1 * (1.f + erff(t1 * 0.70710678118654752f));
                        long idx = (long)(off + grow) * ldc + gc;
                        *(uint32_t*)&C16[idx] = pack2h(o0, o1);
                    }
                } else if (EPI == 3) {
                    int ent = stok_s[lrow];
                    if (ent >= 0) {
                        float w = g_gate[ent];
                        long idx = (long)(ent >> 1) * ldc + gc;
                        atomicAdd(&C[idx],     w * (v0 + bias[gc]));
                        atomicAdd(&C[idx + 1], w * (v1 + bias[gc + 1]));
                    }
                } else {  // EPI == 4
                    long idx = (long)grow * ldc + gc;
                    *(uint32_t*)&C16[idx] = pack2h(v0, v1);
                }
            }
        }
    }
}

// ================= fused flash attention (fp16, 64-row KV chunks) ===========
#define FL_Q   0
#define FL_KST 16384
#define FL_SMEM 49152
__global__ void __launch_bounds__(256, 2) flash_k(
    const half_t* __restrict__ QKV, half_t* __restrict__ O)
{
    extern __shared__ char dsm[];
    uint32_t sb = smem_u32(dsm);
    int tid = threadIdx.x, wid = tid >> 5, lid = tid & 31;
    int bh = blockIdx.y, b = bh >> 3, h = bh & 7;
    int q0 = blockIdx.x * 128;

    long qbase = (long)b * Sc * QKVN + (long)q0 * QKVN + h * HEADc;
    long kb0   = (long)b * Sc * QKVN + 512 + h * HEADc;
    long vb0   = (long)b * Sc * QKVN + 1024 + h * HEADc;
    long obase = (long)b * Sc * Dc + (long)q0 * Dc + h * HEADc;

    auto load_q = [&]() {
#pragma unroll
        for (int i = 0; i < 4; i++) {
            int idx = tid + (i << 8);
            int row = idx >> 3, c16 = idx & 7;
            uint32_t d = SWZ((uint32_t)(row * 128 + c16 * 16));
            CP16(sb + FL_Q + d, QKV + qbase + (long)row * QKVN + c16 * 8, 16);
        }
    };
    auto load_kv = [&](int c, int st) {
        uint32_t kstg = sb + FL_KST + (uint32_t)st * 16384;
        uint32_t vstg = kstg + 8192;
#pragma unroll
        for (int i = 0; i < 2; i++) {
            int idx = tid + (i << 8);
            int row = idx >> 3, c16 = idx & 7;
            uint32_t d = SWZ((uint32_t)(row * 128 + c16 * 16));
            CP16(kstg + d, QKV + kb0 + (long)(c * 64 + row) * QKVN + c16 * 8, 16);
        }
#pragma unroll
        for (int i = 0; i < 2; i++) {
            int idx = tid + (i << 8);
            int row = idx >> 3, c16 = idx & 7;
            uint32_t d = SWZ((uint32_t)(row * 128 + c16 * 16));
            CP16(vstg + d, QKV + vb0 + (long)(c * 64 + row) * QKVN + c16 * 8, 16);
        }
        CP_COMMIT();
    };

    load_q(); load_kv(0, 0);
    load_kv(1, 1);

    int wm = wid * 16;
    int lr = lid >> 2, lc = (lid & 3) * 2;
    int a_row = wm + (lid & 15), a_cb = (lid >> 4) << 4;
    int b_row8 = ((lid >> 4) << 3) + (lid & 7);
    int b_cb = ((lid >> 3) & 1) << 4;
    int v_soff = (lid & 7) + (((lid >> 3) & 1) << 3);
    int v_doff = ((lid >> 4) & 1) << 3;

    uint32_t qF[4][4];
    float m0r = -1e30f, m1r = -1e30f, l0r = 0.f, l1r = 0.f;
    float acc_o[8][4] = {};

    for (int c = 0; c < 16; c++) {
        if (c < 15) asm volatile("cp.async.wait_group 1;" ::: "memory");
        else        asm volatile("cp.async.wait_group 0;" ::: "memory");
        __syncthreads();

        if (c == 0) {
#pragma unroll
            for (int ks = 0; ks < 4; ks++) {
                uint32_t o = SWZ((uint32_t)(a_row * 128 + ks * 32 + a_cb));
                ldsm4(qF[ks], sb + FL_Q + o);
            }
        }
        uint32_t kstg = sb + FL_KST + (uint32_t)(c & 1) * 16384;
        uint32_t vstg = kstg + 8192;

        float s_acc[8][4] = {};
#pragma unroll
        for (int ks = 0; ks < 4; ks++) {
            int kb = ks * 32;
            uint32_t kF[4][4];
#pragma unroll
            for (int g = 0; g < 4; g++) {
                uint32_t o = SWZ((uint32_t)((g * 16 + b_row8) * 128 + kb + b_cb));
                ldsm4(kF[g], kstg + o);
            }
#pragma unroll
            for (int nt = 0; nt < 8; nt++) {
                int g = nt >> 1, pr = (nt & 1) * 2;
                mma_f16(s_acc[nt], qF[ks], kF[g][pr], kF[g][pr + 1]);
            }
        }

        float t0 = -1e30f, t1 = -1e30f;
#pragma unroll
        for (int nt = 0; nt < 8; nt++) {
#pragma unroll
            for (int j = 0; j < 4; j++) s_acc[nt][j] *= 0.125f;
            t0 = fmaxf(t0, fmaxf(s_acc[nt][0], s_acc[nt][1]));
            t1 = fmaxf(t1, fmaxf(s_acc[nt][2], s_acc[nt][3]));
        }
#pragma unroll
        for (int o = 1; o <= 2; o <<= 1) {
            t0 = fmaxf(t0, __shfl_xor_sync(0xffffffffu, t0, o));
            t1 = fmaxf(t1, __shfl_xor_sync(0xffffffffu, t1, o));
        }
        float mn0 = fmaxf(m0r, t0), mn1 = fmaxf(m1r, t1);
        float cor0 = expf(m0r - mn0), cor1 = expf(m1r - mn1);
        float rs0 = 0.f, rs1 = 0.f;
#pragma unroll
        for (int nt = 0; nt < 8; nt++) {
            s_acc[nt][0] = expf(s_acc[nt][0] - mn0);
            s_acc[nt][1] = expf(s_acc[nt][1] - mn0);
            s_acc[nt][2] = expf(s_acc[nt][2] - mn1);
            s_acc[nt][3] = expf(s_acc[nt][3] - mn1);
            rs0 += s_acc[nt][0] + s_acc[nt][1];
            rs1 += s_acc[nt][2] + s_acc[nt][3];
        }
#pragma unroll
        for (int o = 1; o <= 2; o <<= 1) {
            rs0 += __shfl_xor_sync(0xffffffffu, rs0, o);
            rs1 += __shfl_xor_sync(0xffffffffu, rs1, o);
        }
        l0r = l0r * cor0 + rs0; l1r = l1r * cor1 + rs1;
        m0r = mn0; m1r = mn1;
#pragma unroll
        for (int nt = 0; nt < 8; nt++) {
            acc_o[nt][0] *= cor0; acc_o[nt][1] *= cor0;
            acc_o[nt][2] *= cor1; acc_o[nt][3] *= cor1;
        }

#pragma unroll
        for (int kt = 0; kt < 4; kt++) {
            uint32_t aP[4];
            aP[0] = pack2h(s_acc[2 * kt][0],     s_acc[2 * kt][1]);
            aP[1] = pack2h(s_acc[2 * kt][2],     s_acc[2 * kt][3]);
            aP[2] = pack2h(s_acc[2 * kt + 1][0], s_acc[2 * kt + 1][1]);
            aP[3] = pack2h(s_acc[2 * kt + 1][2], s_acc[2 * kt + 1][3]);
            uint32_t vF[4][4];
#pragma unroll
            for (int g = 0; g < 4; g++) {
                uint32_t o = SWZ((uint32_t)((kt * 16 + v_soff) * 128 +
                                            (g * 16 + v_doff) * 2));
                ldsm4t(vF[g], vstg + o);
            }
#pragma unroll
            for (int nt = 0; nt < 8; nt++) {
                int g = nt >> 1, pr = (nt & 1) * 2;
                mma_f16(acc_o[nt], aP, vF[g][pr], vF[g][pr + 1]);
            }
        }
        __syncthreads();
        if (c + 2 < 16) load_kv(c + 2, c & 1);
    }

    float inv0 = 1.f / l0r, inv1 = 1.f / l1r;
    long r0g = obase + (long)(wm + lr) * Dc;
    long r1g = obase + (long)(wm + lr + 8) * Dc;
#pragma unroll
    for (int nt = 0; nt < 8; nt++) {
        int gc = nt * 8 + lc;
        *(uint32_t*)&O[r0g + gc] = pack2h(acc_o[nt][0] * inv0, acc_o[nt][1] * inv0);
        *(uint32_t*)&O[r1g + gc] = pack2h(acc_o[nt][2] * inv1, acc_o[nt][3] * inv1);
    }
}

// ================= transpose + fp16 convert ================================
__global__ void tconv(const float* __restrict__ in, half_t* __restrict__ o16,
                      int R, int Ccol, long sin, long sout)
{
    __shared__ float t[32][33];
    long ib = (long)blockIdx.z * sin, ob = (long)blockIdx.z * sout;
    int c0 = blockIdx.x * 32, r0 = blockIdx.y * 32;
    int tx = threadIdx.x, ty = threadIdx.y;
#pragma unroll
    for (int j = 0; j < 4; j++)
        t[ty + j * 8][tx] = in[ib + (long)(r0 + ty + j * 8) * Ccol + c0 + tx];
    __syncthreads();
#pragma unroll
    for (int j = 0; j < 4; j++) {
        float v = t[tx][ty + j * 8];
        o16[ob + (long)(c0 + ty + j * 8) * R + r0 + tx] = __float2half_rn(v);
    }
}

// ================= elementwise kernels ======================================
__global__ void ln_k(const float* __restrict__ x, const float* __restrict__ w,
                     const float* __restrict__ b, float* __restrict__ out,
                     half_t* __restrict__ o16, int isLn2) {
    int row = blockIdx.x;
    int tid = threadIdx.x;
    if (isLn2 && row == 0 && tid < Ec) g_cnt[tid] = 0;
    const float* xr = x + (long)row * Dc;
    float4 v = *(const float4*)&xr[tid * 4];
    float s = v.x + v.y + v.z + v.w;
    float s2 = v.x * v.x + v.y * v.y + v.z * v.z + v.w * v.w;
    __shared__ float sh[4], sh2[4];
#pragma unroll
    for (int o = 16; o > 0; o >>= 1) {
        s  += __shfl_xor_sync(0xffffffffu, s, o);
        s2 += __shfl_xor_sync(0xffffffffu, s2, o);
    }
    if ((tid & 31) == 0) { sh[tid >> 5] = s; sh2[tid >> 5] = s2; }
    __syncthreads();
    float a = 0.f, a2 = 0.f;
#pragma unroll
    for (int i = 0; i < 4; i++) { a += sh[i]; a2 += sh2[i]; }
    float mu  = a * (1.f / Dc);
    float var = a2 * (1.f / Dc) - mu * mu;
    float inv = rsqrtf(var + 1e-6f);
    int d = tid * 4;
    const float4 wv = *(const float4*)&w[d];
    const float4 bv = *(const float4*)&b[d];
    float y0 = (v.x - mu) * inv * wv.x + bv.x;
    float y1 = (v.y - mu) * inv * wv.y + bv.y;
    float y2 = (v.z - mu) * inv * wv.z + bv.z;
    float y3 = (v.w - mu) * inv * wv.w + bv.w;
    long idx = (long)row * Dc + d;
    if (isLn2) *(float4*)&out[idx] = make_float4(y0, y1, y2, y3);
    *(uint32_t*)&o16[idx] = pack2h(y0, y1);
    *(uint32_t*)&o16[idx + 2] = pack2h(y2, y3);
}

__global__ void gate_k(const float* __restrict__ h, const float* __restrict__ gw) {
    int t = blockIdx.x * 4 + (threadIdx.x >> 5);
    int lid = threadIdx.x & 31;
    const float* hr = h + (long)t * Dc;
    float acc[Ec] = {};
    for (int d = lid; d < Dc; d += 32) {
        float hv = hr[d];
#pragma unroll
        for (int e = 0; e < Ec; e++) acc[e] += hv * gw[d * Ec + e];
    }
#pragma unroll
    for (int e = 0; e < Ec; e++)
#pragma unroll
        for (int o = 16; o > 0; o >>= 1)
            acc[e] += __shfl_xor_sync(0xffffffffu, acc[e], o);
    if (lid == 0) {
        int i0 = 0; float v0 = acc[0];
#pragma unroll
        for (int e = 1; e < Ec; e++) if (acc[e] > v0) { v0 = acc[e]; i0 = e; }
        int i1 = -1; float v1 = -3.4e38f;
#pragma unroll
        for (int e = 0; e < Ec; e++) if (e != i0 && acc[e] > v1) { v1 = acc[e]; i1 = e; }
        float g1 = 1.f / (1.f + expf(v0 - v1));
        g_topi[t * 2] = i0; g_topi[t * 2 + 1] = i1;
        g_gate[t * 2] = 1.f - g1; g_gate[t * 2 + 1] = g1;
        atomicAdd(&g_cnt[i0], 1);
        atomicAdd(&g_cnt[i1], 1);
    }
}

__global__ void offsets_k() {
    if (threadIdx.x == 0) {
        int o = 0, nb = 0;
        for (int e = 0; e < Ec; e++) {
            g_off[e] = o; g_cur[e] = o;
            int c = g_cnt[e];
            int nbe = (c + 127) >> 7;
            for (int j = 0; j < nbe; j++) { g_blk_e[nb] = e; g_blk_m[nb] = j; nb++; }
            o += c;
        }
        g_nblk = nb;
    }
}

__global__ void scatter_k() {
    int i = blockIdx.x * 256 + threadIdx.x;
    if (i >= 2 * Tc) return;
    int e = g_topi[i];
    int pos = atomicAdd(&g_cur[e], 1);
    g_tok[pos] = i;
}

// ================= host =====================================================
template <typename... Args>
static inline void launch_pdl(void* fn, dim3 grid, dim3 block, size_t smem,
                              cudaStream_t st, Args... args) {
    void* argp[] = { (void*)&args... };
    cudaLaunchAttribute attr[1];
    attr[0].id = cudaLaunchAttributeProgrammaticStreamSerialization;
    attr[0].val.programmaticStreamSerializationAllowed = 1;
    cudaLaunchConfig_t cfg;
    cfg.gridDim = grid; cfg.blockDim = block;
    cfg.dynamicSmemBytes = smem; cfg.stream = st;
    cfg.attrs = attr; cfg.numAttrs = 1;
    cudaLaunchKernelExC(&cfg, fn, argp);
}

extern "C" void kernel_launch(void* const* d_in, const int* in_sizes, int n_in,
                              void* d_out, int out_size)
{
    const float* x      = (const float*)d_in[0];
    const float* ln1_w  = (const float*)d_in[1];
    const float* ln1_b  = (const float*)d_in[2];
    const float* wq     = (const float*)d_in[3];
    const float* wk     = (const float*)d_in[4];
    const float* wv     = (const float*)d_in[5];
    const float* wo     = (const float*)d_in[6];
    const float* bo     = (const float*)d_in[7];
    const float* ln2_w  = (const float*)d_in[8];
    const float* ln2_b  = (const float*)d_in[9];
    const float* gate_w = (const float*)d_in[10];
    const float* w1     = (const float*)d_in[11];
    const float* b1     = (const float*)d_in[12];
    const float* w2     = (const float*)d_in[13];
    const float* b2     = (const float*)d_in[14];
    float* out = (float*)d_out;

    float *ph;
    half_t *ph16, *pqkv16, *pao16, *phm16;
    half_t *wqkvt16, *wot16, *w1t16, *w2t16;
    cudaGetSymbolAddress((void**)&ph, g_h);
    cudaGetSymbolAddress((void**)&ph16, g_h16);
    cudaGetSymbolAddress((void**)&pqkv16, g_qkv16);
    cudaGetSymbolAddress((void**)&pao16, g_ao16);
    cudaGetSymbolAddress((void**)&phm16, g_hm16);
    cudaGetSymbolAddress((void**)&wqkvt16, g_wqkvt16);
    cudaGetSymbolAddress((void**)&wot16, g_wot16);
    cudaGetSymbolAddress((void**)&w1t16, g_w1t16);
    cudaGetSymbolAddress((void**)&w2t16, g_w2t16);

    cudaFuncSetAttribute(tgemm<128, 4, 0, 1>, cudaFuncAttributeMaxDynamicSharedMemorySize, TG_SMEM_BN(128));
    cudaFuncSetAttribute(tgemm<64,  1, 0, 1>, cudaFuncAttributeMaxDynamicSharedMemorySize, TG_SMEM_BN(64));
    cudaFuncSetAttribute(tgemm<128, 2, 1, 0>, cudaFuncAttributeMaxDynamicSharedMemorySize, TG_SMEM_BN(128));
    cudaFuncSetAttribute(tgemm<128, 3, 2, 0>, cudaFuncAttributeMaxDynamicSharedMemorySize, TG_SMEM_BN(128));
    cudaFuncSetAttribute(flash_k, cudaFuncAttributeMaxDynamicSharedMemorySize, FL_SMEM);

    cudaStream_t s1;
    cudaStreamCreateWithFlags(&s1, cudaStreamNonBlocking);
    cudaEvent_t eFork, eQKV[Lc], eWO[Lc], eMOE[Lc];
    cudaEventCreateWithFlags(&eFork, cudaEventDisableTiming);
    for (int l = 0; l < Lc; l++) {
        cudaEventCreateWithFlags(&eQKV[l], cudaEventDisableTiming);
        cudaEventCreateWithFlags(&eWO[l], cudaEventDisableTiming);
        cudaEventCreateWithFlags(&eMOE[l], cudaEventDisableTiming);
    }

    dim3 tcb(32, 8);
    cudaEventRecord(eFork, 0);
    cudaStreamWaitEvent(s1, eFork, 0);
    for (int l = 0; l < Lc; l++) {
        half_t* qt = wqkvt16 + (long)l * QKVN * Dc;
        tconv<<<dim3(16, 16, 1), tcb, 0, s1>>>(wq + (long)l * Dc * Dc, qt, Dc, Dc, 0, 0);
        tconv<<<dim3(16, 16, 1), tcb, 0, s1>>>(wk + (long)l * Dc * Dc, qt + 512 * Dc, Dc, Dc, 0, 0);
        tconv<<<dim3(16, 16, 1), tcb, 0, s1>>>(wv + (long)l * Dc * Dc, qt + 1024 * Dc, Dc, Dc, 0, 0);
        cudaEventRecord(eQKV[l], s1);
        tconv<<<dim3(16, 16, 1), tcb, 0, s1>>>(wo + (long)l * Dc * Dc,
            wot16 + (long)l * Dc * Dc, Dc, Dc, 0, 0);
        cudaEventRecord(eWO[l], s1);
        tconv<<<dim3(DHc / 32, Dc / 32, Ec), tcb, 0, s1>>>(
            w1 + (long)l * Ec * Dc * DHc, w1t16 + (long)l * Ec * Dc * DHc,
            Dc, DHc, (long)Dc * DHc, (long)Dc * DHc);
        tconv<<<dim3(Dc / 32, DHc / 32, Ec), tcb, 0, s1>>>(
            w2 + (long)l * Ec * DHc * Dc, w2t16 + (long)l * Ec * DHc * Dc,
            DHc, Dc, (long)DHc * Dc, (long)DHc * Dc);
        cudaEventRecord(eMOE[l], s1);
    }

    for (int l = 0; l < Lc; l++) {
        half_t* qt = wqkvt16 + (long)l * QKVN * Dc;
        const float* resid = (l == 0) ? x : out;

        ln_k<<<Tc, 128>>>(resid, ln1_w + l * Dc, ln1_b + l * Dc, ph, ph16, 0);

        cudaStreamWaitEvent(0, eQKV[l], 0);
        launch_pdl((void*)tgemm<128, 4, 0, 1>, dim3(QKVN / 128, 32, 1), dim3(256),
                   TG_SMEM_BN(128), 0,
                   (int)Dc, (const half_t*)ph16, (int)Dc, (const half_t*)qt, (int)Dc,
                   (float*)nullptr, pqkv16, (int)QKVN,
                   (const float*)nullptr, (const float*)nullptr, 0L, 0L);

        flash_k<<<dim3(Sc / 128, Bc * Hc), 256, FL_SMEM>>>(pqkv16, pao16);

        cudaStreamWaitEvent(0, eWO[l], 0);
        launch_pdl((void*)tgemm<64, 1, 0, 1>, dim3(Dc / 64, 32, 1), dim3(256),
                   TG_SMEM_BN(64), 0,
                   (int)Dc, (const half_t*)pao16, (int)Dc,
                   (const half_t*)(wot16 + (long)l * Dc * Dc), (int)Dc,
                   out, (half_t*)nullptr, (int)Dc,
                   bo + l * Dc, resid, 0L, 0L);

        ln_k<<<Tc, 128>>>(out, ln2_w + l * Dc, ln2_b + l * Dc, ph, ph16, 1);

        gate_k<<<Tc / 4, 128>>>(ph, gate_w + (long)l * Dc * Ec);
        offsets_k<<<1, 1>>>();
        scatter_k<<<2 * Tc / 256, 256>>>();

        cudaStreamWaitEvent(0, eMOE[l], 0);
        tgemm<128, 2, 1, 0><<<dim3(16, MAXBLK, 1), 256, TG_SMEM_BN(128)>>>(
            Dc, ph16, Dc, w1t16 + (long)l * Ec * Dc * DHc, Dc,
            nullptr, phm16, DHc,
            b1 + (long)l * Ec * DHc, nullptr, (long)Dc * DHc, DHc);
        tgemm<128, 3, 2, 0><<<dim3(4, MAXBLK, 1), 256, TG_SMEM_BN(128)>>>(
            DHc, phm16, DHc, w2t16 + (long)l * Ec * DHc * Dc, DHc,
            out, nullptr, Dc,
            b2 + (long)l * Ec * Dc, nullptr, (long)DHc * Dc, Dc);
    }
}

// round 17
// speedup vs baseline: 1.0064x; 1.0064x over previous
#include <cuda_runtime.h>
#include <cuda_fp16.h>
#include <math.h>
#include <stdint.h>

#define Tc 4096
#define Dc 512
#define Sc 1024
#define Bc 4
#define Hc 8
#define HEADc 64
#define Ec 8
#define DHc 2048
#define Lc 2
#define QKVN 1536
#define MAXBLK 72

typedef __half half_t;

// ---------------- scratch (device globals) ---------------------------------
__device__ float  g_h[Tc * Dc];
__device__ half_t g_h16[Tc * Dc];
__device__ half_t g_qkv16[(size_t)Tc * QKVN];
__device__ half_t g_ao16[Tc * Dc];
__device__ half_t g_hm16[(size_t)2 * Tc * DHc];
__device__ half_t g_wqkvt16[(size_t)Lc * QKVN * Dc];
__device__ half_t g_wot16[Lc * Dc * Dc];
__device__ half_t g_w1t16[(size_t)Lc * Ec * Dc * DHc];
__device__ half_t g_w2t16[(size_t)Lc * Ec * Dc * DHc];
__device__ float  g_gate[Tc * 2];
__device__ int    g_topi[Tc * 2];
__device__ int    g_cnt[Ec], g_cur[Ec], g_off[Ec];
__device__ int    g_tok[2 * Tc];
__device__ int    g_blk_e[MAXBLK], g_blk_m[MAXBLK], g_nblk;

// ================= low-level helpers ========================================
__device__ __forceinline__ uint32_t smem_u32(const void* p) {
    uint32_t a;
    asm("{ .reg .u64 t; cvta.to.shared.u64 t, %1; cvt.u32.u64 %0, t; }"
        : "=r"(a) : "l"(p));
    return a;
}
#define SWZ(o) ((o) ^ (((o) >> 3) & 0x70))
#define CP16(dst, src, sz) \
    asm volatile("cp.async.cg.shared.global [%0], [%1], 16, %2;" \
                 :: "r"(dst), "l"(src), "r"(sz) : "memory")
#define CP_COMMIT() asm volatile("cp.async.commit_group;" ::: "memory")

__device__ __forceinline__ void ldsm4(uint32_t* r, uint32_t addr) {
    asm volatile("ldmatrix.sync.aligned.m8n8.x4.shared.b16 {%0,%1,%2,%3}, [%4];"
                 : "=r"(r[0]), "=r"(r[1]), "=r"(r[2]), "=r"(r[3]) : "r"(addr));
}
__device__ __forceinline__ void ldsm4t(uint32_t* r, uint32_t addr) {
    asm volatile("ldmatrix.sync.aligned.m8n8.x4.trans.shared.b16 {%0,%1,%2,%3}, [%4];"
                 : "=r"(r[0]), "=r"(r[1]), "=r"(r[2]), "=r"(r[3]) : "r"(addr));
}
__device__ __forceinline__ void mma_f16(float* d, const uint32_t* a,
                                        uint32_t b0, uint32_t b1) {
    asm volatile(
        "mma.sync.aligned.m16n8k16.row.col.f32.f16.f16.f32 "
        "{%0,%1,%2,%3}, {%4,%5,%6,%7}, {%8,%9}, {%0,%1,%2,%3};"
        : "+f"(d[0]), "+f"(d[1]), "+f"(d[2]), "+f"(d[3])
        : "r"(a[0]), "r"(a[1]), "r"(a[2]), "r"(a[3]), "r"(b0), "r"(b1));
}
__device__ __forceinline__ uint32_t pack2h(float x0, float x1) {
    __half2 h = __floats2half2_rn(x0, x1);
    return *(uint32_t*)&h;
}

// ================= pipelined fp16 tensor GEMM (3-stage, 2 CTAs/SM) ==========
// R15-proven mainloop. BN templated (128 or 64 n-tile). No PDL.
// EPI: 1 fp32+bias+Resid->C; 2 gelu(+bias)->fp16 grouped;
//      3 gate-weighted atomicAdd into fp32 out; 4 fp16 plain
// AMODE: 0 direct; 1 grouped + gather rows via g_tok>>1; 2 grouped rows off+m
#define TG_SMEM_BN(BN) (3 * (16384 + (BN) * 128) + 1024)
template <int BN, int EPI, int AMODE>
__global__ void __launch_bounds__(256, 2) tgemm(
    int K,
    const half_t* __restrict__ A, int lda,
    const half_t* __restrict__ B, int ldb,
    float* __restrict__ C, half_t* __restrict__ C16, int ldc,
    const float* __restrict__ bias, const float* __restrict__ Resid,
    long wstride, long bstride)
{
    constexpr int NWN = BN / 32, NWM = 8 / NWN, MT = 128 / (16 * NWM);
    constexpr uint32_t ASZ = 16384u;
    constexpr uint32_t STG = ASZ + (uint32_t)BN * 128u;
    extern __shared__ char dsm[];
    __shared__ int stok_s[128];
    uint32_t sbb = smem_u32(dsm);
    uint32_t tb = (sbb + 1023) & ~1023u;
    int tid = threadIdx.x, wid = tid >> 5, lid = tid & 31;

    int cnt = 0, off = 0, m0, n0;
    if (AMODE != 0) {
        int by = blockIdx.y;
        if (by >= g_nblk) return;
        int e = g_blk_e[by];
        cnt = g_cnt[e]; off = g_off[e];
        m0 = g_blk_m[by] * 128;
        B += (long)e * wstride;
        bias += (long)e * bstride;
    } else {
        m0 = blockIdx.y * 128;
    }
    n0 = blockIdx.x * BN;

    if (AMODE == 1 && tid < 128) {
        int i = m0 + tid;
        stok_s[tid] = (i < cnt) ? (g_tok[off + i] >> 1) : -1;
    }
    if (AMODE == 2 && tid < 128) {
        int i = m0 + tid;
        stok_s[tid] = (i < cnt) ? g_tok[off + i] : -1;
    }
    if (AMODE != 0) __syncthreads();

    auto load_stage = [&](int c, int st) {
        uint32_t base = tb + (uint32_t)st * STG;
        int k0 = c << 6;
#pragma unroll
        for (int i = 0; i < 4; i++) {
            int idx = tid + (i << 8);
            int row = idx >> 3, c16 = idx & 7;
            uint32_t d = SWZ((uint32_t)(row * 128 + c16 * 16));
            long so; uint32_t sz = 16;
            if (AMODE == 0) so = (long)(m0 + row) * lda + k0 + c16 * 8;
            else if (AMODE == 1) {
                int tk = stok_s[row];
                if (tk < 0) { sz = 0; tk = 0; }
                so = (long)tk * lda + k0 + c16 * 8;
            } else {
                if (stok_s[row] < 0) { sz = 0; so = 0; }
                else so = (long)(off + m0 + row) * lda + k0 + c16 * 8;
            }
            CP16(base + d, A + so, sz);
        }
#pragma unroll
        for (int i = 0; i < BN / 32; i++) {
            int idx = tid + (i << 8);
            int row = idx >> 3, c16 = idx & 7;
            uint32_t d = SWZ((uint32_t)(row * 128 + c16 * 16));
            long so = (long)(n0 + row) * ldb + k0 + c16 * 8;
            CP16(base + ASZ + d, B + so, 16);
        }
        CP_COMMIT();
    };

    int wm = (wid / NWN) * (MT * 16), wn = (wid % NWN) * 32;
    int a_row = wm + (lid & 15), a_cb = (lid >> 4) << 4;
    int b_row = wn + ((lid >> 4) << 3) + (lid & 7), b_cb = ((lid >> 3) & 1) << 4;
    float acc[MT][4][4] = {};

    int nch = K >> 6;
    load_stage(0, 0);
    if (nch > 1) load_stage(1, 1);
    int st = 0;
    for (int c = 0; c < nch; c++) {
        if (c + 2 < nch) {
            load_stage(c + 2, (st + 2) % 3);
            asm volatile("cp.async.wait_group 2;" ::: "memory");
        } else if (c + 1 < nch) {
            asm volatile("cp.async.wait_group 1;" ::: "memory");
        } else {
            asm volatile("cp.async.wait_group 0;" ::: "memory");
        }
        __syncthreads();
        uint32_t base = tb + (uint32_t)st * STG;

        uint32_t bF[2][2][4];
#pragma unroll
        for (int g = 0; g < 2; g++) {
            uint32_t o = SWZ((uint32_t)((b_row + g * 16) * 128 + 0 + b_cb));
            ldsm4(bF[0][g], base + ASZ + o);
        }
#pragma unroll
        for (int ks = 0; ks < 4; ks++) {
            int cur = ks & 1, nxt = cur ^ 1;
            if (ks < 3) {
                int kb = (ks + 1) * 32;
#pragma unroll
                for (int g = 0; g < 2; g++) {
                    uint32_t o = SWZ((uint32_t)((b_row + g * 16) * 128 + kb + b_cb));
                    ldsm4(bF[nxt][g], base + ASZ + o);
                }
            }
            int kb = ks * 32;
#pragma unroll
            for (int mt = 0; mt < MT; mt++) {
                uint32_t aF[4];
                uint32_t o = SWZ((uint32_t)((a_row + mt * 16) * 128 + kb + a_cb));
                ldsm4(aF, base + o);
#pragma unroll
                for (int nt = 0; nt < 4; nt++) {
                    int g = nt >> 1, pr = (nt & 1) * 2;
                    mma_f16(acc[mt][nt], aF, bF[cur][g][pr], bF[cur][g][pr + 1]);
                }
            }
        }
        __syncthreads();
        st = (st + 1) % 3;
    }

    // ---- register epilogue ----
    int lr = lid >> 2, lc = (lid & 3) * 2;
#pragma unroll
    for (int mt = 0; mt < MT; mt++) {
#pragma unroll
        for (int half = 0; half < 2; half++) {
            int lrow = wm + mt * 16 + lr + half * 8;
            int grow = m0 + lrow;
#pragma unroll
            for (int nt = 0; nt < 4; nt++) {
                float v0 = acc[mt][nt][half * 2 + 0];
                float v1 = acc[mt][nt][half * 2 + 1];
                int gc = n0 + wn + nt * 8 + lc;
                if (EPI == 1) {
                    long idx = (long)grow * ldc + gc;
                    float2 old = *(const float2*)&Resid[idx];
                    *(float2*)&C[idx] = make_float2(v0 + bias[gc] + old.x,
                                                    v1 + bias[gc + 1] + old.y);
                } else if (EPI == 2) {
                    if (stok_s[lrow] >= 0) {
                        float t0 = v0 + bias[gc], t1 = v1 + bias[gc + 1];
                        float o0 = 0.5f * t0 * (1.f + erff(t0 * 0.70710678118654752f));
                        float o1 = 0.5f * t1 * (1.f + erff(t1 * 0.70710678118654752f));
                        long idx = (long)(off + grow) * ldc + gc;
                        *(uint32_t*)&C16[idx] = pack2h(o0, o1);
                    }
                } else if (EPI == 3) {
                    int ent = stok_s[lrow];
                    if (ent >= 0) {
                        float w = g_gate[ent];
                        long idx = (long)(ent >> 1) * ldc + gc;
                        atomicAdd(&C[idx],     w * (v0 + bias[gc]));
                        atomicAdd(&C[idx + 1], w * (v1 + bias[gc + 1]));
                    }
                } else {  // EPI == 4
                    long idx = (long)grow * ldc + gc;
                    *(uint32_t*)&C16[idx] = pack2h(v0, v1);
                }
            }
        }
    }
}

// ================= fused flash attention (fp16, 64-row KV chunks) ===========
#define FL_Q   0
#define FL_KST 16384
#define FL_SMEM 49152
__global__ void __launch_bounds__(256, 2) flash_k(
    const half_t* __restrict__ QKV, half_t* __restrict__ O)
{
    extern __shared__ char dsm[];
    uint32_t sb = smem_u32(dsm);
    int tid = threadIdx.x, wid = tid >> 5, lid = tid & 31;
    int bh = blockIdx.y, b = bh >> 3, h = bh & 7;
    int q0 = blockIdx.x * 128;

    long qbase = (long)b * Sc * QKVN + (long)q0 * QKVN + h * HEADc;
    long kb0   = (long)b * Sc * QKVN + 512 + h * HEADc;
    long vb0   = (long)b * Sc * QKVN + 1024 + h * HEADc;
    long obase = (long)b * Sc * Dc + (long)q0 * Dc + h * HEADc;

    auto load_q = [&]() {
#pragma unroll
        for (int i = 0; i < 4; i++) {
            int idx = tid + (i << 8);
            int row = idx >> 3, c16 = idx & 7;
            uint32_t d = SWZ((uint32_t)(row * 128 + c16 * 16));
            CP16(sb + FL_Q + d, QKV + qbase + (long)row * QKVN + c16 * 8, 16);
        }
    };
    auto load_kv = [&](int c, int st) {
        uint32_t kstg = sb + FL_KST + (uint32_t)st * 16384;
        uint32_t vstg = kstg + 8192;
#pragma unroll
        for (int i = 0; i < 2; i++) {
            int idx = tid + (i << 8);
            int row = idx >> 3, c16 = idx & 7;
            uint32_t d = SWZ((uint32_t)(row * 128 + c16 * 16));
            CP16(kstg + d, QKV + kb0 + (long)(c * 64 + row) * QKVN + c16 * 8, 16);
        }
#pragma unroll
        for (int i = 0; i < 2; i++) {
            int idx = tid + (i << 8);
            int row = idx >> 3, c16 = idx & 7;
            uint32_t d = SWZ((uint32_t)(row * 128 + c16 * 16));
            CP16(vstg + d, QKV + vb0 + (long)(c * 64 + row) * QKVN + c16 * 8, 16);
        }
        CP_COMMIT();
    };

    load_q(); load_kv(0, 0);
    load_kv(1, 1);

    int wm = wid * 16;
    int lr = lid >> 2, lc = (lid & 3) * 2;
    int a_row = wm + (lid & 15), a_cb = (lid >> 4) << 4;
    int b_row8 = ((lid >> 4) << 3) + (lid & 7);
    int b_cb = ((lid >> 3) & 1) << 4;
    int v_soff = (lid & 7) + (((lid >> 3) & 1) << 3);
    int v_doff = ((lid >> 4) & 1) << 3;

    uint32_t qF[4][4];
    float m0r = -1e30f, m1r = -1e30f, l0r = 0.f, l1r = 0.f;
    float acc_o[8][4] = {};

    for (int c = 0; c < 16; c++) {
        if (c < 15) asm volatile("cp.async.wait_group 1;" ::: "memory");
        else        asm volatile("cp.async.wait_group 0;" ::: "memory");
        __syncthreads();

        if (c == 0) {
#pragma unroll
            for (int ks = 0; ks < 4; ks++) {
                uint32_t o = SWZ((uint32_t)(a_row * 128 + ks * 32 + a_cb));
                ldsm4(qF[ks], sb + FL_Q + o);
            }
        }
        uint32_t kstg = sb + FL_KST + (uint32_t)(c & 1) * 16384;
        uint32_t vstg = kstg + 8192;

        float s_acc[8][4] = {};
#pragma unroll
        for (int ks = 0; ks < 4; ks++) {
            int kb = ks * 32;
            uint32_t kF[4][4];
#pragma unroll
            for (int g = 0; g < 4; g++) {
                uint32_t o = SWZ((uint32_t)((g * 16 + b_row8) * 128 + kb + b_cb));
                ldsm4(kF[g], kstg + o);
            }
#pragma unroll
            for (int nt = 0; nt < 8; nt++) {
                int g = nt >> 1, pr = (nt & 1) * 2;
                mma_f16(s_acc[nt], qF[ks], kF[g][pr], kF[g][pr + 1]);
            }
        }

        float t0 = -1e30f, t1 = -1e30f;
#pragma unroll
        for (int nt = 0; nt < 8; nt++) {
#pragma unroll
            for (int j = 0; j < 4; j++) s_acc[nt][j] *= 0.125f;
            t0 = fmaxf(t0, fmaxf(s_acc[nt][0], s_acc[nt][1]));
            t1 = fmaxf(t1, fmaxf(s_acc[nt][2], s_acc[nt][3]));
        }
#pragma unroll
        for (int o = 1; o <= 2; o <<= 1) {
            t0 = fmaxf(t0, __shfl_xor_sync(0xffffffffu, t0, o));
            t1 = fmaxf(t1, __shfl_xor_sync(0xffffffffu, t1, o));
        }
        float mn0 = fmaxf(m0r, t0), mn1 = fmaxf(m1r, t1);
        float cor0 = expf(m0r - mn0), cor1 = expf(m1r - mn1);
        float rs0 = 0.f, rs1 = 0.f;
#pragma unroll
        for (int nt = 0; nt < 8; nt++) {
            s_acc[nt][0] = expf(s_acc[nt][0] - mn0);
            s_acc[nt][1] = expf(s_acc[nt][1] - mn0);
            s_acc[nt][2] = expf(s_acc[nt][2] - mn1);
            s_acc[nt][3] = expf(s_acc[nt][3] - mn1);
            rs0 += s_acc[nt][0] + s_acc[nt][1];
            rs1 += s_acc[nt][2] + s_acc[nt][3];
        }
#pragma unroll
        for (int o = 1; o <= 2; o <<= 1) {
            rs0 += __shfl_xor_sync(0xffffffffu, rs0, o);
            rs1 += __shfl_xor_sync(0xffffffffu, rs1, o);
        }
        l0r = l0r * cor0 + rs0; l1r = l1r * cor1 + rs1;
        m0r = mn0; m1r = mn1;
#pragma unroll
        for (int nt = 0; nt < 8; nt++) {
            acc_o[nt][0] *= cor0; acc_o[nt][1] *= cor0;
            acc_o[nt][2] *= cor1; acc_o[nt][3] *= cor1;
        }

#pragma unroll
        for (int kt = 0; kt < 4; kt++) {
            uint32_t aP[4];
            aP[0] = pack2h(s_acc[2 * kt][0],     s_acc[2 * kt][1]);
            aP[1] = pack2h(s_acc[2 * kt][2],     s_acc[2 * kt][3]);
            aP[2] = pack2h(s_acc[2 * kt + 1][0], s_acc[2 * kt + 1][1]);
            aP[3] = pack2h(s_acc[2 * kt + 1][2], s_acc[2 * kt + 1][3]);
            uint32_t vF[4][4];
#pragma unroll
            for (int g = 0; g < 4; g++) {
                uint32_t o = SWZ((uint32_t)((kt * 16 + v_soff) * 128 +
                                            (g * 16 + v_doff) * 2));
                ldsm4t(vF[g], vstg + o);
            }
#pragma unroll
            for (int nt = 0; nt < 8; nt++) {
                int g = nt >> 1, pr = (nt & 1) * 2;
                mma_f16(acc_o[nt], aP, vF[g][pr], vF[g][pr + 1]);
            }
        }
        __syncthreads();
        if (c + 2 < 16) load_kv(c + 2, c & 1);
    }

    float inv0 = 1.f / l0r, inv1 = 1.f / l1r;
    long r0g = obase + (long)(wm + lr) * Dc;
    long r1g = obase + (long)(wm + lr + 8) * Dc;
#pragma unroll
    for (int nt = 0; nt < 8; nt++) {
        int gc = nt * 8 + lc;
        *(uint32_t*)&O[r0g + gc] = pack2h(acc_o[nt][0] * inv0, acc_o[nt][1] * inv0);
        *(uint32_t*)&O[r1g + gc] = pack2h(acc_o[nt][2] * inv1, acc_o[nt][3] * inv1);
    }
}

// ================= transpose + fp16 convert ================================
__global__ void tconv(const float* __restrict__ in, half_t* __restrict__ o16,
                      int R, int Ccol, long sin, long sout)
{
    __shared__ float t[32][33];
    long ib = (long)blockIdx.z * sin, ob = (long)blockIdx.z * sout;
    int c0 = blockIdx.x * 32, r0 = blockIdx.y * 32;
    int tx = threadIdx.x, ty = threadIdx.y;
#pragma unroll
    for (int j = 0; j < 4; j++)
        t[ty + j * 8][tx] = in[ib + (long)(r0 + ty + j * 8) * Ccol + c0 + tx];
    __syncthreads();
#pragma unroll
    for (int j = 0; j < 4; j++) {
        float v = t[tx][ty + j * 8];
        o16[ob + (long)(c0 + ty + j * 8) * R + r0 + tx] = __float2half_rn(v);
    }
}

// ================= elementwise kernels ======================================
__global__ void ln_k(const float* __restrict__ x, const float* __restrict__ w,
                     const float* __restrict__ b, float* __restrict__ out,
                     half_t* __restrict__ o16, int isLn2) {
    int row = blockIdx.x;
    int tid = threadIdx.x;
    if (isLn2 && row == 0 && tid < Ec) g_cnt[tid] = 0;
    const float* xr = x + (long)row * Dc;
    float4 v = *(const float4*)&xr[tid * 4];
    float s = v.x + v.y + v.z + v.w;
    float s2 = v.x * v.x + v.y * v.y + v.z * v.z + v.w * v.w;
    __shared__ float sh[4], sh2[4];
#pragma unroll
    for (int o = 16; o > 0; o >>= 1) {
        s  += __shfl_xor_sync(0xffffffffu, s, o);
        s2 += __shfl_xor_sync(0xffffffffu, s2, o);
    }
    if ((tid & 31) == 0) { sh[tid >> 5] = s; sh2[tid >> 5] = s2; }
    __syncthreads();
    float a = 0.f, a2 = 0.f;
#pragma unroll
    for (int i = 0; i < 4; i++) { a += sh[i]; a2 += sh2[i]; }
    float mu  = a * (1.f / Dc);
    float var = a2 * (1.f / Dc) - mu * mu;
    float inv = rsqrtf(var + 1e-6f);
    int d = tid * 4;
    const float4 wv = *(const float4*)&w[d];
    const float4 bv = *(const float4*)&b[d];
    float y0 = (v.x - mu) * inv * wv.x + bv.x;
    float y1 = (v.y - mu) * inv * wv.y + bv.y;
    float y2 = (v.z - mu) * inv * wv.z + bv.z;
    float y3 = (v.w - mu) * inv * wv.w + bv.w;
    long idx = (long)row * Dc + d;
    if (isLn2) *(float4*)&out[idx] = make_float4(y0, y1, y2, y3);
    *(uint32_t*)&o16[idx] = pack2h(y0, y1);
    *(uint32_t*)&o16[idx + 2] = pack2h(y2, y3);
}

__global__ void gate_k(const float* __restrict__ h, const float* __restrict__ gw) {
    int t = blockIdx.x * 4 + (threadIdx.x >> 5);
    int lid = threadIdx.x & 31;
    const float* hr = h + (long)t * Dc;
    float acc[Ec] = {};
    for (int d = lid; d < Dc; d += 32) {
        float hv = hr[d];
#pragma unroll
        for (int e = 0; e < Ec; e++) acc[e] += hv * gw[d * Ec + e];
    }
#pragma unroll
    for (int e = 0; e < Ec; e++)
#pragma unroll
        for (int o = 16; o > 0; o >>= 1)
            acc[e] += __shfl_xor_sync(0xffffffffu, acc[e], o);
    if (lid == 0) {
        int i0 = 0; float v0 = acc[0];
#pragma unroll
        for (int e = 1; e < Ec; e++) if (acc[e] > v0) { v0 = acc[e]; i0 = e; }
        int i1 = -1; float v1 = -3.4e38f;
#pragma unroll
        for (int e = 0; e < Ec; e++) if (e != i0 && acc[e] > v1) { v1 = acc[e]; i1 = e; }
        float g1 = 1.f / (1.f + expf(v0 - v1));
        g_topi[t * 2] = i0; g_topi[t * 2 + 1] = i1;
        g_gate[t * 2] = 1.f - g1; g_gate[t * 2 + 1] = g1;
        atomicAdd(&g_cnt[i0], 1);
        atomicAdd(&g_cnt[i1], 1);
    }
}

__global__ void offsets_k() {
    if (threadIdx.x == 0) {
        int o = 0, nb = 0;
        for (int e = 0; e < Ec; e++) {
            g_off[e] = o; g_cur[e] = o;
            int c = g_cnt[e];
            int nbe = (c + 127) >> 7;
            for (int j = 0; j < nbe; j++) { g_blk_e[nb] = e; g_blk_m[nb] = j; nb++; }
            o += c;
        }
        g_nblk = nb;
    }
}

__global__ void scatter_k() {
    int i = blockIdx.x * 256 + threadIdx.x;
    if (i >= 2 * Tc) return;
    int e = g_topi[i];
    int pos = atomicAdd(&g_cur[e], 1);
    g_tok[pos] = i;
}

// ================= host =====================================================
extern "C" void kernel_launch(void* const* d_in, const int* in_sizes, int n_in,
                              void* d_out, int out_size)
{
    const float* x      = (const float*)d_in[0];
    const float* ln1_w  = (const float*)d_in[1];
    const float* ln1_b  = (const float*)d_in[2];
    const float* wq     = (const float*)d_in[3];
    const float* wk     = (const float*)d_in[4];
    const float* wv     = (const float*)d_in[5];
    const float* wo     = (const float*)d_in[6];
    const float* bo     = (const float*)d_in[7];
    const float* ln2_w  = (const float*)d_in[8];
    const float* ln2_b  = (const float*)d_in[9];
    const float* gate_w = (const float*)d_in[10];
    const float* w1     = (const float*)d_in[11];
    const float* b1     = (const float*)d_in[12];
    const float* w2     = (const float*)d_in[13];
    const float* b2     = (const float*)d_in[14];
    float* out = (float*)d_out;

    float *ph;
    half_t *ph16, *pqkv16, *pao16, *phm16;
    half_t *wqkvt16, *wot16, *w1t16, *w2t16;
    cudaGetSymbolAddress((void**)&ph, g_h);
    cudaGetSymbolAddress((void**)&ph16, g_h16);
    cudaGetSymbolAddress((void**)&pqkv16, g_qkv16);
    cudaGetSymbolAddress((void**)&pao16, g_ao16);
    cudaGetSymbolAddress((void**)&phm16, g_hm16);
    cudaGetSymbolAddress((void**)&wqkvt16, g_wqkvt16);
    cudaGetSymbolAddress((void**)&wot16, g_wot16);
    cudaGetSymbolAddress((void**)&w1t16, g_w1t16);
    cudaGetSymbolAddress((void**)&w2t16, g_w2t16);

    cudaFuncSetAttribute(tgemm<128, 4, 0>, cudaFuncAttributeMaxDynamicSharedMemorySize, TG_SMEM_BN(128));
    cudaFuncSetAttribute(tgemm<64,  1, 0>, cudaFuncAttributeMaxDynamicSharedMemorySize, TG_SMEM_BN(64));
    cudaFuncSetAttribute(tgemm<128, 2, 1>, cudaFuncAttributeMaxDynamicSharedMemorySize, TG_SMEM_BN(128));
    cudaFuncSetAttribute(tgemm<128, 3, 2>, cudaFuncAttributeMaxDynamicSharedMemorySize, TG_SMEM_BN(128));
    cudaFuncSetAttribute(flash_k, cudaFuncAttributeMaxDynamicSharedMemorySize, FL_SMEM);

    cudaStream_t s1;
    cudaStreamCreateWithFlags(&s1, cudaStreamNonBlocking);
    cudaEvent_t eFork, eQKV[Lc], eWO[Lc], eMOE[Lc];
    cudaEventCreateWithFlags(&eFork, cudaEventDisableTiming);
    for (int l = 0; l < Lc; l++) {
        cudaEventCreateWithFlags(&eQKV[l], cudaEventDisableTiming);
        cudaEventCreateWithFlags(&eWO[l], cudaEventDisableTiming);
        cudaEventCreateWithFlags(&eMOE[l], cudaEventDisableTiming);
    }

    dim3 tcb(32, 8);
    cudaEventRecord(eFork, 0);
    cudaStreamWaitEvent(s1, eFork, 0);
    for (int l = 0; l < Lc; l++) {
        half_t* qt = wqkvt16 + (long)l * QKVN * Dc;
        tconv<<<dim3(16, 16, 1), tcb, 0, s1>>>(wq + (long)l * Dc * Dc, qt, Dc, Dc, 0, 0);
        tconv<<<dim3(16, 16, 1), tcb, 0, s1>>>(wk + (long)l * Dc * Dc, qt + 512 * Dc, Dc, Dc, 0, 0);
        tconv<<<dim3(16, 16, 1), tcb, 0, s1>>>(wv + (long)l * Dc * Dc, qt + 1024 * Dc, Dc, Dc, 0, 0);
        cudaEventRecord(eQKV[l], s1);
        tconv<<<dim3(16, 16, 1), tcb, 0, s1>>>(wo + (long)l * Dc * Dc,
            wot16 + (long)l * Dc * Dc, Dc, Dc, 0, 0);
        cudaEventRecord(eWO[l], s1);
        tconv<<<dim3(DHc / 32, Dc / 32, Ec), tcb, 0, s1>>>(
            w1 + (long)l * Ec * Dc * DHc, w1t16 + (long)l * Ec * Dc * DHc,
            Dc, DHc, (long)Dc * DHc, (long)Dc * DHc);
        tconv<<<dim3(Dc / 32, DHc / 32, Ec), tcb, 0, s1>>>(
            w2 + (long)l * Ec * DHc * Dc, w2t16 + (long)l * Ec * DHc * Dc,
            DHc, Dc, (long)DHc * Dc, (long)DHc * Dc);
        cudaEventRecord(eMOE[l], s1);
    }

    for (int l = 0; l < Lc; l++) {
        half_t* qt = wqkvt16 + (long)l * QKVN * Dc;
        const float* resid = (l == 0) ? x : out;

        ln_k<<<Tc, 128>>>(resid, ln1_w + l * Dc, ln1_b + l * Dc, ph, ph16, 0);

        cudaStreamWaitEvent(0, eQKV[l], 0);
        tgemm<128, 4, 0><<<dim3(QKVN / 128, 32, 1), 256, TG_SMEM_BN(128)>>>(
            Dc, ph16, Dc, qt, Dc,
            nullptr, pqkv16, QKVN, nullptr, nullptr, 0, 0);

        flash_k<<<dim3(Sc / 128, Bc * Hc), 256, FL_SMEM>>>(pqkv16, pao16);

        cudaStreamWaitEvent(0, eWO[l], 0);
        tgemm<64, 1, 0><<<dim3(Dc / 64, 32, 1), 256, TG_SMEM_BN(64)>>>(
            Dc, pao16, Dc, wot16 + (long)l * Dc * Dc, Dc,
            out, nullptr, Dc, bo + l * Dc, resid, 0, 0);

        ln_k<<<Tc, 128>>>(out, ln2_w + l * Dc, ln2_b + l * Dc, ph, ph16, 1);

        gate_k<<<Tc / 4, 128>>>(ph, gate_w + (long)l * Dc * Ec);
        offsets_k<<<1, 1>>>();
        scatter_k<<<2 * Tc / 256, 256>>>();

        cudaStreamWaitEvent(0, eMOE[l], 0);
        tgemm<128, 2, 1><<<dim3(16, MAXBLK, 1), 256, TG_SMEM_BN(128)>>>(
            Dc, ph16, Dc, w1t16 + (long)l * Ec * Dc * DHc, Dc,
            nullptr, phm16, DHc,
            b1 + (long)l * Ec * DHc, nullptr, (long)Dc * DHc, DHc);
        tgemm<128, 3, 2><<<dim3(4, MAXBLK, 1), 256, TG_SMEM_BN(128)>>>(
            DHc, phm16, DHc, w2t16 + (long)l * Ec * DHc * Dc, DHc,
            out, nullptr, Dc,
            b2 + (long)l * Ec * Dc, nullptr, (long)DHc * Dc, Dc);
    }
}